// round 8
// baseline (speedup 1.0000x reference)
#include <cuda_runtime.h>

#define DIM   100
#define NW    39
#define NH    4
#define NBLK  4800
#define NTHR  256
#define NWARP 8
#define NQ    25          // float4 chunks per 100-float row
#define RPW   5           // rows per warp (ceil(39/8))

typedef unsigned long long u64;

__device__ __forceinline__ u64 f2fma(u64 a, u64 b, u64 c) {
    u64 d; asm("fma.rn.f32x2 %0, %1, %2, %3;" : "=l"(d) : "l"(a), "l"(b), "l"(c)); return d;
}
__device__ __forceinline__ u64 f2mul(u64 a, u64 b) {
    u64 d; asm("mul.rn.f32x2 %0, %1, %2;" : "=l"(d) : "l"(a), "l"(b)); return d;
}
__device__ __forceinline__ u64 f2add(u64 a, u64 b) {
    u64 d; asm("add.rn.f32x2 %0, %1, %2;" : "=l"(d) : "l"(a), "l"(b)); return d;
}
__device__ __forceinline__ float f2sum(u64 a) {
    float lo, hi; asm("mov.b64 {%0, %1}, %2;" : "=f"(lo), "=f"(hi) : "l"(a)); return lo + hi;
}
__device__ __forceinline__ u64 f2bc(float v) {
    u64 r; asm("mov.b64 %0, {%1, %2};" : "=l"(r) : "f"(v), "f"(v)); return r;
}

#define C65  0x3F2666663F266666ull   // (0.65f, 0.65f)
#define C35  0x3EB333333EB33333ull   // (0.35f, 0.35f)
#define ABSM 0x7FFFFFFF7FFFFFFFull

__global__ __launch_bounds__(NTHR, 4)
void tse_kernel(const float* __restrict__ x,
                const float* __restrict__ w_att,
                const float* __restrict__ b_att,
                float* __restrict__ out)
{
    __shared__ __align__(16) float se[40 * NH];             // exp(scores) [n][h]
    __shared__ float sinv[NH];
    __shared__ __align__(16) ulonglong2 sp4[NWARP * NH * NQ]; // partials (12.8 KB)

    const int tid  = threadIdx.x;
    const int warp = tid >> 5;
    const int lane = tid & 31;
    const int bid  = blockIdx.x;
    const float* __restrict__ xb = x + bid * (40 * DIM);
    const bool act = (lane < NQ);

    // ---- register-resident params as f32x2 pairs (A=(x,y), B=(z,w)) ----
    u64 tA = 0, tB = 0;
    u64 waA[NH], waB[NH], baA[NH], baB[NH];
    #pragma unroll
    for (int h = 0; h < NH; h++) { waA[h] = waB[h] = baA[h] = baB[h] = 0; }
    if (act) {
        const ulonglong2 tt = reinterpret_cast<const ulonglong2*>(xb)[lane];
        tA = tt.x; tB = tt.y;
        #pragma unroll
        for (int h = 0; h < NH; h++) {
            const ulonglong2 wv = *reinterpret_cast<const ulonglong2*>(w_att + h * DIM + 4 * lane);
            const ulonglong2 bv = *reinterpret_cast<const ulonglong2*>(b_att + h * DIM + 4 * lane);
            waA[h] = wv.x; waB[h] = wv.y;
            baA[h] = bv.x; baB[h] = bv.y;
        }
    }

    const float* __restrict__ rp = xb + DIM + 4 * lane;

    // ---- phase 1: double-buffered row loads, packed score math ----
    u64 wcA = 0, wcB = 0;
    if (act) {
        const ulonglong2 v = *reinterpret_cast<const ulonglong2*>(rp + warp * DIM);
        wcA = v.x; wcB = v.y;
    }

    #pragma unroll
    for (int k = 0; k < RPW; k++) {
        const int n = warp + k * NWARP;
        u64 wnA = 0, wnB = 0;
        if (k + 1 < RPW) {
            const int n2 = warp + (k + 1) * NWARP;
            if (act && n2 < NW) {
                const ulonglong2 v = *reinterpret_cast<const ulonglong2*>(rp + n2 * DIM);
                wnA = v.x; wnB = v.y;
            }
        }

        float a[NH];
        #pragma unroll
        for (int h = 0; h < NH; h++) {
            const u64 pA = f2fma(wcA, waA[h], baA[h]);
            const u64 pB = f2fma(wcB, waB[h], baB[h]);
            // leaky: 0.65*p + 0.35*|p|  (== p for p>=0, 0.3p for p<0)
            const u64 hA = f2fma(pA, C65, f2mul(pA & ABSM, C35));
            const u64 hB = f2fma(pB, C65, f2mul(pB & ABSM, C35));
            const u64 s2 = f2fma(tA, hA, f2fma(tB, hB, 0ull));
            a[h] = f2sum(s2);
        }

        // packed reduction: lanes 0-7 -> h0, 8-15 -> h1, 16-23 -> h2, 24-31 -> h3
        const bool lo = (lane < 16);
        float xv = __shfl_xor_sync(0xffffffffu, lo ? a[2] : a[0], 16);
        float yv = __shfl_xor_sync(0xffffffffu, lo ? a[3] : a[1], 16);
        float u0 = (lo ? a[0] : a[2]) + xv;
        float u1 = (lo ? a[1] : a[3]) + yv;
        const bool b3 = (lane & 8) != 0;
        float zv = __shfl_xor_sync(0xffffffffu, b3 ? u0 : u1, 8);
        float t  = (b3 ? u1 : u0) + zv;
        t += __shfl_xor_sync(0xffffffffu, t, 4);
        t += __shfl_xor_sync(0xffffffffu, t, 2);
        t += __shfl_xor_sync(0xffffffffu, t, 1);
        if (((lane & 7) == 0) && n < NW) se[n * NH + (lane >> 3)] = __expf(t);

        wcA = wnA; wcB = wnB;
    }
    __syncthreads();

    // ---- phase 2: normalizers, one warp per head ----
    if (warp < NH) {
        float s = (lane < NW) ? se[lane * NH + warp] : 0.f;
        if (lane + 32 < NW) s += se[(lane + 32) * NH + warp];
        #pragma unroll
        for (int off = 16; off; off >>= 1)
            s += __shfl_xor_sync(0xffffffffu, s, off);
        if (lane == 0) sinv[warp] = 1.f / s;
    }
    __syncthreads();

    // ---- phase 3: rows re-loaded (L1-hot), packed accumulate ----
    u64 accA[NH], accB[NH];
    #pragma unroll
    for (int h = 0; h < NH; h++) { accA[h] = 0; accB[h] = 0; }

    wcA = wcB = 0;
    if (act) {
        const ulonglong2 v = *reinterpret_cast<const ulonglong2*>(rp + warp * DIM);
        wcA = v.x; wcB = v.y;
    }

    #pragma unroll
    for (int k = 0; k < RPW; k++) {
        const int n = warp + k * NWARP;
        u64 wnA = 0, wnB = 0;
        if (k + 1 < RPW) {
            const int n2 = warp + (k + 1) * NWARP;
            if (act && n2 < NW) {
                const ulonglong2 v = *reinterpret_cast<const ulonglong2*>(rp + n2 * DIM);
                wnA = v.x; wnB = v.y;
            }
        }

        float4 e4 = make_float4(0.f, 0.f, 0.f, 0.f);
        if (n < NW) e4 = *reinterpret_cast<const float4*>(se + n * NH);  // broadcast
        const u64 e0 = f2bc(e4.x), e1 = f2bc(e4.y), e2 = f2bc(e4.z), e3 = f2bc(e4.w);
        accA[0] = f2fma(e0, wcA, accA[0]); accB[0] = f2fma(e0, wcB, accB[0]);
        accA[1] = f2fma(e1, wcA, accA[1]); accB[1] = f2fma(e1, wcB, accB[1]);
        accA[2] = f2fma(e2, wcA, accA[2]); accB[2] = f2fma(e2, wcB, accB[2]);
        accA[3] = f2fma(e3, wcA, accA[3]); accB[3] = f2fma(e3, wcB, accB[3]);

        wcA = wnA; wcB = wnB;
    }

    // ---- per-warp partials ----
    if (act) {
        #pragma unroll
        for (int h = 0; h < NH; h++) {
            ulonglong2 v; v.x = accA[h]; v.y = accB[h];
            sp4[(warp * NH + h) * NQ + lane] = v;
        }
    }
    __syncthreads();

    // ---- cross-warp reduce + normalize + coalesced 16B store ----
    if (tid < NH * NQ) {
        const int h = tid / NQ;
        const int i = tid - h * NQ;
        ulonglong2 v = sp4[h * NQ + i];
        #pragma unroll
        for (int w = 1; w < NWARP; w++) {
            const ulonglong2 p = sp4[(w * NH + h) * NQ + i];
            v.x = f2add(v.x, p.x);
            v.y = f2add(v.y, p.y);
        }
        const u64 si2 = f2bc(sinv[h]);
        v.x = f2mul(v.x, si2);
        v.y = f2mul(v.y, si2);
        reinterpret_cast<ulonglong2*>(out + bid * (NH * DIM))[tid] = v;
    }
}

extern "C" void kernel_launch(void* const* d_in, const int* in_sizes, int n_in,
                              void* d_out, int out_size)
{
    const float* x     = (const float*)d_in[0];
    const float* w_att = (const float*)d_in[1];
    const float* b_att = (const float*)d_in[2];
    float* out = (float*)d_out;
    tse_kernel<<<NBLK, NTHR>>>(x, w_att, b_att, out);
}

// round 9
// speedup vs baseline: 1.1043x; 1.1043x over previous
#include <cuda_runtime.h>

#define DIM   100
#define NW    39
#define NH    4
#define NBLK  4800
#define NTHR  256
#define NWARP 8
#define NQ    25          // float4 chunks per 100-float row
#define RPW   5           // rows per warp (ceil(39/8))

__device__ __forceinline__ float sgn035(float t) {
    // copysign(0.35f, t) via bit ops
    return __uint_as_float((__float_as_uint(t) & 0x80000000u) | 0x3EB33333u);
}

__global__ __launch_bounds__(NTHR, 4)
void tse_kernel(const float* __restrict__ x,
                const float* __restrict__ w_att,
                const float* __restrict__ b_att,
                float* __restrict__ out)
{
    __shared__ __align__(16) float se[40 * NH];             // exp(scores) [n][h]
    __shared__ float sinv[NH];
    __shared__ __align__(16) float4 sp4[NWARP * NH * NQ];   // partials (12.8 KB)

    const int tid  = threadIdx.x;
    const int warp = tid >> 5;
    const int lane = tid & 31;
    const int bid  = blockIdx.x;
    const float* __restrict__ xb = x + bid * (40 * DIM);
    const bool act = (lane < NQ);

    // ---- register params: r1 = t*wa, b1 = t*ba, k35 = copysign(0.35, t) ----
    float4 r1[NH], b1[NH], k35;
    #pragma unroll
    for (int h = 0; h < NH; h++) {
        r1[h] = make_float4(0.f, 0.f, 0.f, 0.f);
        b1[h] = make_float4(0.f, 0.f, 0.f, 0.f);
    }
    k35 = make_float4(0.f, 0.f, 0.f, 0.f);
    if (act) {
        const float4 t4 = reinterpret_cast<const float4*>(xb)[lane];
        k35.x = sgn035(t4.x); k35.y = sgn035(t4.y);
        k35.z = sgn035(t4.z); k35.w = sgn035(t4.w);
        #pragma unroll
        for (int h = 0; h < NH; h++) {
            const float4 wv = *reinterpret_cast<const float4*>(w_att + h * DIM + 4 * lane);
            const float4 bv = *reinterpret_cast<const float4*>(b_att + h * DIM + 4 * lane);
            r1[h].x = t4.x * wv.x; r1[h].y = t4.y * wv.y;
            r1[h].z = t4.z * wv.z; r1[h].w = t4.w * wv.w;
            b1[h].x = t4.x * bv.x; b1[h].y = t4.y * bv.y;
            b1[h].z = t4.z * bv.z; b1[h].w = t4.w * bv.w;
        }
    }

    const float* __restrict__ rp = xb + DIM + 4 * lane;

    // ---- phase 1: double-buffered row loads, 3-FFMA/element score math ----
    float4 w_cur = make_float4(0.f, 0.f, 0.f, 0.f);
    if (act) w_cur = *reinterpret_cast<const float4*>(rp + warp * DIM);

    #pragma unroll
    for (int k = 0; k < RPW; k++) {
        const int n = warp + k * NWARP;
        float4 w_nxt = make_float4(0.f, 0.f, 0.f, 0.f);
        if (k + 1 < RPW) {
            const int n2 = warp + (k + 1) * NWARP;
            if (act && n2 < NW)
                w_nxt = *reinterpret_cast<const float4*>(rp + n2 * DIM);
        }

        float a[NH];
        #pragma unroll
        for (int h = 0; h < NH; h++) {
            float y, sa, sb;
            y  = fmaf(w_cur.x, r1[h].x, b1[h].x);
            sa = y * 0.65f;
            sb = k35.x * fabsf(y);
            y  = fmaf(w_cur.y, r1[h].y, b1[h].y);
            sa = fmaf(y, 0.65f, sa);
            sb = fmaf(k35.y, fabsf(y), sb);
            y  = fmaf(w_cur.z, r1[h].z, b1[h].z);
            sa = fmaf(y, 0.65f, sa);
            sb = fmaf(k35.z, fabsf(y), sb);
            y  = fmaf(w_cur.w, r1[h].w, b1[h].w);
            sa = fmaf(y, 0.65f, sa);
            sb = fmaf(k35.w, fabsf(y), sb);
            a[h] = sa + sb;
        }

        // packed reduction: lanes 0-7 -> h0, 8-15 -> h1, 16-23 -> h2, 24-31 -> h3
        const bool lo = (lane < 16);
        float xv = __shfl_xor_sync(0xffffffffu, lo ? a[2] : a[0], 16);
        float yv = __shfl_xor_sync(0xffffffffu, lo ? a[3] : a[1], 16);
        float u0 = (lo ? a[0] : a[2]) + xv;
        float u1 = (lo ? a[1] : a[3]) + yv;
        const bool b3 = (lane & 8) != 0;
        float zv = __shfl_xor_sync(0xffffffffu, b3 ? u0 : u1, 8);
        float t  = (b3 ? u1 : u0) + zv;
        t += __shfl_xor_sync(0xffffffffu, t, 4);
        t += __shfl_xor_sync(0xffffffffu, t, 2);
        t += __shfl_xor_sync(0xffffffffu, t, 1);
        if (((lane & 7) == 0) && n < NW) se[n * NH + (lane >> 3)] = __expf(t);

        w_cur = w_nxt;
    }
    __syncthreads();

    // ---- phase 2: normalizers, one warp per head ----
    if (warp < NH) {
        float s = (lane < NW) ? se[lane * NH + warp] : 0.f;
        if (lane + 32 < NW) s += se[(lane + 32) * NH + warp];
        #pragma unroll
        for (int off = 16; off; off >>= 1)
            s += __shfl_xor_sync(0xffffffffu, s, off);
        if (lane == 0) sinv[warp] = 1.f / s;
    }
    __syncthreads();

    // ---- phase 3: rows re-loaded (L1-hot) with double-buffer ----
    float4 acc[NH];
    #pragma unroll
    for (int h = 0; h < NH; h++) acc[h] = make_float4(0.f, 0.f, 0.f, 0.f);

    w_cur = make_float4(0.f, 0.f, 0.f, 0.f);
    if (act) w_cur = *reinterpret_cast<const float4*>(rp + warp * DIM);

    #pragma unroll
    for (int k = 0; k < RPW; k++) {
        const int n = warp + k * NWARP;
        float4 w_nxt = make_float4(0.f, 0.f, 0.f, 0.f);
        if (k + 1 < RPW) {
            const int n2 = warp + (k + 1) * NWARP;
            if (act && n2 < NW)
                w_nxt = *reinterpret_cast<const float4*>(rp + n2 * DIM);
        }

        float4 e4 = make_float4(0.f, 0.f, 0.f, 0.f);
        if (n < NW) e4 = *reinterpret_cast<const float4*>(se + n * NH);  // broadcast
        acc[0].x = fmaf(e4.x, w_cur.x, acc[0].x); acc[0].y = fmaf(e4.x, w_cur.y, acc[0].y);
        acc[0].z = fmaf(e4.x, w_cur.z, acc[0].z); acc[0].w = fmaf(e4.x, w_cur.w, acc[0].w);
        acc[1].x = fmaf(e4.y, w_cur.x, acc[1].x); acc[1].y = fmaf(e4.y, w_cur.y, acc[1].y);
        acc[1].z = fmaf(e4.y, w_cur.z, acc[1].z); acc[1].w = fmaf(e4.y, w_cur.w, acc[1].w);
        acc[2].x = fmaf(e4.z, w_cur.x, acc[2].x); acc[2].y = fmaf(e4.z, w_cur.y, acc[2].y);
        acc[2].z = fmaf(e4.z, w_cur.z, acc[2].z); acc[2].w = fmaf(e4.z, w_cur.w, acc[2].w);
        acc[3].x = fmaf(e4.w, w_cur.x, acc[3].x); acc[3].y = fmaf(e4.w, w_cur.y, acc[3].y);
        acc[3].z = fmaf(e4.w, w_cur.z, acc[3].z); acc[3].w = fmaf(e4.w, w_cur.w, acc[3].w);

        w_cur = w_nxt;
    }

    // ---- per-warp partials ----
    if (act) {
        #pragma unroll
        for (int h = 0; h < NH; h++)
            sp4[(warp * NH + h) * NQ + lane] = acc[h];
    }
    __syncthreads();

    // ---- cross-warp reduce + normalize + coalesced float4 store ----
    if (tid < NH * NQ) {
        const int h = tid / NQ;
        const int i = tid - h * NQ;
        float4 v = sp4[h * NQ + i];
        #pragma unroll
        for (int w = 1; w < NWARP; w++) {
            const float4 p = sp4[(w * NH + h) * NQ + i];
            v.x += p.x; v.y += p.y; v.z += p.z; v.w += p.w;
        }
        const float si = sinv[h];
        v.x *= si; v.y *= si; v.z *= si; v.w *= si;
        reinterpret_cast<float4*>(out + bid * (NH * DIM))[tid] = v;
    }
}

extern "C" void kernel_launch(void* const* d_in, const int* in_sizes, int n_in,
                              void* d_out, int out_size)
{
    const float* x     = (const float*)d_in[0];
    const float* w_att = (const float*)d_in[1];
    const float* b_att = (const float*)d_in[2];
    float* out = (float*)d_out;
    tse_kernel<<<NBLK, NTHR>>>(x, w_att, b_att, out);
}

// round 10
// speedup vs baseline: 1.1665x; 1.0564x over previous
#include <cuda_runtime.h>

#define DIM   100
#define NW    39
#define NH    4
#define NBLK  4800
#define NTHR  256
#define NWARP 8
#define NQ    25          // float4 chunks per 100-float row
#define RPW   5           // rows per warp (ceil(39/8))

__device__ __forceinline__ float sgn035(float t) {
    return __uint_as_float((__float_as_uint(t) & 0x80000000u) | 0x3EB33333u);
}

__global__ __launch_bounds__(NTHR, 4)
void tse_kernel(const float* __restrict__ x,
                const float* __restrict__ w_att,
                const float* __restrict__ b_att,
                float* __restrict__ out)
{
    __shared__ __align__(16) float se[40 * NH];             // exp(scores) [n][h] (warp-local use)
    __shared__ float sz[NWARP * NH];                        // per-warp Z partials
    __shared__ __align__(16) float4 sp4[NWARP * NH * NQ];   // partials (12.8 KB)

    const int tid  = threadIdx.x;
    const int warp = tid >> 5;
    const int lane = tid & 31;
    const int bid  = blockIdx.x;
    const float* __restrict__ xb = x + bid * (40 * DIM);
    const bool act = (lane < NQ);

    // ---- register params: r1 = t*wa, b1 = t*ba, k35 = copysign(0.35, t) ----
    float4 r1[NH], b1[NH], k35;
    #pragma unroll
    for (int h = 0; h < NH; h++) {
        r1[h] = make_float4(0.f, 0.f, 0.f, 0.f);
        b1[h] = make_float4(0.f, 0.f, 0.f, 0.f);
    }
    k35 = make_float4(0.f, 0.f, 0.f, 0.f);
    if (act) {
        const float4 t4 = reinterpret_cast<const float4*>(xb)[lane];
        k35.x = sgn035(t4.x); k35.y = sgn035(t4.y);
        k35.z = sgn035(t4.z); k35.w = sgn035(t4.w);
        #pragma unroll
        for (int h = 0; h < NH; h++) {
            const float4 wv = *reinterpret_cast<const float4*>(w_att + h * DIM + 4 * lane);
            const float4 bv = *reinterpret_cast<const float4*>(b_att + h * DIM + 4 * lane);
            r1[h].x = t4.x * wv.x; r1[h].y = t4.y * wv.y;
            r1[h].z = t4.z * wv.z; r1[h].w = t4.w * wv.w;
            b1[h].x = t4.x * bv.x; b1[h].y = t4.y * bv.y;
            b1[h].z = t4.z * bv.z; b1[h].w = t4.w * bv.w;
        }
    }

    const float* __restrict__ rp = xb + DIM + 4 * lane;

    // ---- phase 1: double-buffered row loads, 3-FFMA/element score math ----
    float zacc = 0.f;
    float4 w_cur = make_float4(0.f, 0.f, 0.f, 0.f);
    if (act) w_cur = *reinterpret_cast<const float4*>(rp + warp * DIM);

    #pragma unroll
    for (int k = 0; k < RPW; k++) {
        const int n = warp + k * NWARP;
        float4 w_nxt = make_float4(0.f, 0.f, 0.f, 0.f);
        if (k + 1 < RPW) {
            const int n2 = warp + (k + 1) * NWARP;
            if (act && n2 < NW)
                w_nxt = *reinterpret_cast<const float4*>(rp + n2 * DIM);
        }

        float a[NH];
        #pragma unroll
        for (int h = 0; h < NH; h++) {
            float y, sa, sb;
            y  = fmaf(w_cur.x, r1[h].x, b1[h].x);
            sa = y * 0.65f;
            sb = k35.x * fabsf(y);
            y  = fmaf(w_cur.y, r1[h].y, b1[h].y);
            sa = fmaf(y, 0.65f, sa);
            sb = fmaf(k35.y, fabsf(y), sb);
            y  = fmaf(w_cur.z, r1[h].z, b1[h].z);
            sa = fmaf(y, 0.65f, sa);
            sb = fmaf(k35.z, fabsf(y), sb);
            y  = fmaf(w_cur.w, r1[h].w, b1[h].w);
            sa = fmaf(y, 0.65f, sa);
            sb = fmaf(k35.w, fabsf(y), sb);
            a[h] = sa + sb;
        }

        // packed reduction: lanes 0-7 -> h0, 8-15 -> h1, 16-23 -> h2, 24-31 -> h3;
        // butterfly leaves the group's total on ALL 8 lanes of the group.
        const bool lo = (lane < 16);
        float xv = __shfl_xor_sync(0xffffffffu, lo ? a[2] : a[0], 16);
        float yv = __shfl_xor_sync(0xffffffffu, lo ? a[3] : a[1], 16);
        float u0 = (lo ? a[0] : a[2]) + xv;
        float u1 = (lo ? a[1] : a[3]) + yv;
        const bool b3 = (lane & 8) != 0;
        float zv = __shfl_xor_sync(0xffffffffu, b3 ? u0 : u1, 8);
        float t  = (b3 ? u1 : u0) + zv;
        t += __shfl_xor_sync(0xffffffffu, t, 4);
        t += __shfl_xor_sync(0xffffffffu, t, 2);
        t += __shfl_xor_sync(0xffffffffu, t, 1);

        const float e = __expf(t);
        if (n < NW) {
            if ((lane & 7) == 0) se[n * NH + (lane >> 3)] = e;
            zacc += e;                  // this lane's group-head Z partial
        }

        w_cur = w_nxt;
    }
    __syncwarp();   // phase 3 reads only this warp's se rows (written by this warp)

    // ---- phase 3: rows re-loaded (L1-hot) with double-buffer ----
    float4 acc[NH];
    #pragma unroll
    for (int h = 0; h < NH; h++) acc[h] = make_float4(0.f, 0.f, 0.f, 0.f);

    w_cur = make_float4(0.f, 0.f, 0.f, 0.f);
    if (act) w_cur = *reinterpret_cast<const float4*>(rp + warp * DIM);

    #pragma unroll
    for (int k = 0; k < RPW; k++) {
        const int n = warp + k * NWARP;
        float4 w_nxt = make_float4(0.f, 0.f, 0.f, 0.f);
        if (k + 1 < RPW) {
            const int n2 = warp + (k + 1) * NWARP;
            if (act && n2 < NW)
                w_nxt = *reinterpret_cast<const float4*>(rp + n2 * DIM);
        }

        float4 e4 = make_float4(0.f, 0.f, 0.f, 0.f);
        if (n < NW) e4 = *reinterpret_cast<const float4*>(se + n * NH);  // warp-local broadcast
        acc[0].x = fmaf(e4.x, w_cur.x, acc[0].x); acc[0].y = fmaf(e4.x, w_cur.y, acc[0].y);
        acc[0].z = fmaf(e4.x, w_cur.z, acc[0].z); acc[0].w = fmaf(e4.x, w_cur.w, acc[0].w);
        acc[1].x = fmaf(e4.y, w_cur.x, acc[1].x); acc[1].y = fmaf(e4.y, w_cur.y, acc[1].y);
        acc[1].z = fmaf(e4.y, w_cur.z, acc[1].z); acc[1].w = fmaf(e4.y, w_cur.w, acc[1].w);
        acc[2].x = fmaf(e4.z, w_cur.x, acc[2].x); acc[2].y = fmaf(e4.z, w_cur.y, acc[2].y);
        acc[2].z = fmaf(e4.z, w_cur.z, acc[2].z); acc[2].w = fmaf(e4.z, w_cur.w, acc[2].w);
        acc[3].x = fmaf(e4.w, w_cur.x, acc[3].x); acc[3].y = fmaf(e4.w, w_cur.y, acc[3].y);
        acc[3].z = fmaf(e4.w, w_cur.z, acc[3].z); acc[3].w = fmaf(e4.w, w_cur.w, acc[3].w);

        w_cur = w_nxt;
    }

    // ---- per-warp partials + Z partials ----
    if (act) {
        #pragma unroll
        for (int h = 0; h < NH; h++)
            sp4[(warp * NH + h) * NQ + lane] = acc[h];
    }
    if ((lane & 7) == 0) sz[warp * NH + (lane >> 3)] = zacc;
    __syncthreads();   // the ONLY block-wide barrier

    // ---- cross-warp reduce + normalize + coalesced float4 store ----
    if (tid < NH * NQ) {
        const int h = tid / NQ;
        const int i = tid - h * NQ;
        float4 v = sp4[h * NQ + i];
        float  Z = sz[h];
        #pragma unroll
        for (int w = 1; w < NWARP; w++) {
            const float4 p = sp4[(w * NH + h) * NQ + i];
            v.x += p.x; v.y += p.y; v.z += p.z; v.w += p.w;
            Z += sz[w * NH + h];
        }
        const float si = 1.f / Z;
        v.x *= si; v.y *= si; v.z *= si; v.w *= si;
        reinterpret_cast<float4*>(out + bid * (NH * DIM))[tid] = v;
    }
}

extern "C" void kernel_launch(void* const* d_in, const int* in_sizes, int n_in,
                              void* d_out, int out_size)
{
    const float* x     = (const float*)d_in[0];
    const float* w_att = (const float*)d_in[1];
    const float* b_att = (const float*)d_in[2];
    float* out = (float*)d_out;
    tse_kernel<<<NBLK, NTHR>>>(x, w_att, b_att, out);
}